// round 14
// baseline (speedup 1.0000x reference)
#include <cuda_runtime.h>
#include <cuda_fp16.h>
#include <stdint.h>

// Problem dims
#define BB 4
#define SS 2048
#define DD 768
#define DQ 64
#define HH 3072
#define RR 8192   // BB*SS

// ---------------- scratch (device globals; no allocation allowed) ----------
__device__ __half g_h    [RR*DD];
__device__ __half g_h2   [RR*DD];
__device__ float  g_y1   [RR*DD];
__device__ __half g_q    [RR*DQ];          // pre-scaled by 1/8
__device__ __half g_k    [RR*DQ];
__device__ __half g_vt   [BB*DQ*SS];       // [batch][d][s]  (V transposed)
__device__ __half g_oh   [RR*DQ];
__device__ __half g_a1   [(long long)RR*HH];
__device__ __half g_wsT  [DD*DQ];          // [n=768][k=64]
__device__ __half g_wqkvT[256*DD];         // [n=256][k=768]
__device__ __half g_f1T  [HH*DD];          // [3072][768]
__device__ __half g_f2T  [DD*HH];          // [768][3072]

__device__ __forceinline__ void cp16(void* dst, const void* src) {
    uint32_t d = (uint32_t)__cvta_generic_to_shared(dst);
    asm volatile("cp.async.cg.shared.global [%0], [%1], 16;\n" :: "r"(d), "l"(src));
}
#define CP_COMMIT() asm volatile("cp.async.commit_group;\n" ::: "memory")
#define CP_WAITG(n) asm volatile("cp.async.wait_group %0;\n" :: "n"(n) : "memory")

__device__ __forceinline__ void mma_f16(float* c, const uint32_t* a, const uint32_t* b) {
    asm volatile(
        "mma.sync.aligned.m16n8k16.row.col.f32.f16.f16.f32 "
        "{%0,%1,%2,%3}, {%4,%5,%6,%7}, {%8,%9}, {%0,%1,%2,%3};\n"
        : "+f"(c[0]), "+f"(c[1]), "+f"(c[2]), "+f"(c[3])
        : "r"(a[0]), "r"(a[1]), "r"(a[2]), "r"(a[3]), "r"(b[0]), "r"(b[1]));
}

__device__ __forceinline__ void ldsm4(uint32_t& r0, uint32_t& r1, uint32_t& r2, uint32_t& r3,
                                      uint32_t a) {
    asm volatile("ldmatrix.sync.aligned.m8n8.x4.shared.b16 {%0,%1,%2,%3}, [%4];"
        : "=r"(r0), "=r"(r1), "=r"(r2), "=r"(r3) : "r"(a));
}

__device__ __forceinline__ uint32_t h2u(__half2 h) {
    return *reinterpret_cast<uint32_t*>(&h);
}

// fast erf-based GELU: Abramowitz-Stegun 7.1.26, |abs err| < 1.5e-7
__device__ __forceinline__ float fast_gelu(float x) {
    float z  = 0.70710678118654752f * x;
    float az = fabsf(z);
    float t  = __fdividef(1.0f, 1.0f + 0.3275911f * az);
    float e  = __expf(-az * az);
    float poly = ((((1.061405429f * t - 1.453152027f) * t + 1.421413741f) * t
                 - 0.284496736f) * t + 0.254829592f) * t;
    float erfv = copysignf(1.0f - poly * e, x);
    return 0.5f * x * (1.0f + erfv);
}

// ---------------- prologue kernels -----------------------------------------
__global__ void zero_kernel(float4* __restrict__ p, int n4) {
    int i = blockIdx.x * blockDim.x + threadIdx.x;
    if (i < n4) p[i] = make_float4(0.f, 0.f, 0.f, 0.f);
}

// WsT[n][k] = half( sum_h lin_w[h*64+k][n] ), tiled transpose (coalesced)
__global__ void wsumT_kernel(const float* __restrict__ w, __half* __restrict__ d) {
    __shared__ float t[32][33];
    int kb = blockIdx.x * 32, nb = blockIdx.y * 32;
    int tx = threadIdx.x, ty = threadIdx.y;
    #pragma unroll
    for (int j = 0; j < 32; j += 8) {
        int k = kb + ty + j, n = nb + tx;
        float s = 0.f;
        #pragma unroll
        for (int h = 0; h < 12; h++) s += w[(h * DQ + k) * DD + n];
        t[ty + j][tx] = s;
    }
    __syncthreads();
    #pragma unroll
    for (int j = 0; j < 32; j += 8)
        d[(nb + ty + j) * DQ + kb + tx] = __float2half(t[tx][ty + j]);
}

// wqkvT[c][r] tiled transpose, c: q|k|v|zero-pad
__global__ void pack_wqkvT_kernel(const float* __restrict__ wq, const float* __restrict__ wk,
                                  const float* __restrict__ wv, __half* __restrict__ d) {
    __shared__ float t[32][33];
    int cb = blockIdx.x * 32, rb = blockIdx.y * 32;
    int tx = threadIdx.x, ty = threadIdx.y;
    const float* src = nullptr; int c0 = 0;
    if (cb < 64)       { src = wq; c0 = cb; }
    else if (cb < 128) { src = wk; c0 = cb - 64; }
    else if (cb < 192) { src = wv; c0 = cb - 128; }
    #pragma unroll
    for (int j = 0; j < 32; j += 8)
        t[ty + j][tx] = src ? src[(rb + ty + j) * DQ + c0 + tx] : 0.f;
    __syncthreads();
    #pragma unroll
    for (int j = 0; j < 32; j += 8)
        d[(long long)(cb + ty + j) * DD + rb + tx] = __float2half(t[tx][ty + j]);
}

__global__ void transposeh_kernel(const float* __restrict__ in, __half* __restrict__ out,
                                  int K, int N) {
    __shared__ float t[32][33];
    int nb = blockIdx.x * 32, kb = blockIdx.y * 32;
    int tx = threadIdx.x, ty = threadIdx.y;
    #pragma unroll
    for (int j = 0; j < 32; j += 8)
        t[ty + j][tx] = in[(long long)(kb + ty + j) * N + nb + tx];
    __syncthreads();
    #pragma unroll
    for (int j = 0; j < 32; j += 8)
        out[(long long)(nb + ty + j) * K + kb + tx] = __float2half(t[tx][ty + j]);
}

// LayerNorm: warp-per-row, float4, shfl-only reduction, no __syncthreads.
__global__ __launch_bounds__(256) void ln_kernel(
    const float* __restrict__ x, const float* __restrict__ g,
    const float* __restrict__ b, __half* __restrict__ o)
{
    const int warp = threadIdx.x >> 5, lane = threadIdx.x & 31;
    const long long row = (long long)blockIdx.x * 8 + warp;
    const float4* xr = (const float4*)(x + row * DD);
    float4 v[6];
    float s1 = 0.f, s2 = 0.f;
    #pragma unroll
    for (int j = 0; j < 6; j++) {
        v[j] = xr[lane + 32 * j];
        s1 += v[j].x + v[j].y + v[j].z + v[j].w;
        s2 += v[j].x * v[j].x + v[j].y * v[j].y + v[j].z * v[j].z + v[j].w * v[j].w;
    }
    #pragma unroll
    for (int off = 16; off; off >>= 1) {
        s1 += __shfl_xor_sync(0xffffffffu, s1, off);
        s2 += __shfl_xor_sync(0xffffffffu, s2, off);
    }
    float mu = s1 * (1.f / 768.f);
    float var = s2 * (1.f / 768.f) - mu * mu;
    float rs = rsqrtf(var + 1e-5f);
    const float4* gr = (const float4*)g;
    const float4* br = (const float4*)b;
    uint2* orow = (uint2*)(o + row * DD);
    #pragma unroll
    for (int j = 0; j < 6; j++) {
        float4 gv = gr[lane + 32 * j], bv = br[lane + 32 * j];
        __half2 h0 = __floats2half2_rn((v[j].x - mu) * rs * gv.x + bv.x,
                                       (v[j].y - mu) * rs * gv.y + bv.y);
        __half2 h1 = __floats2half2_rn((v[j].z - mu) * rs * gv.z + bv.z,
                                       (v[j].w - mu) * rs * gv.w + bv.w);
        orow[lane + 32 * j] = make_uint2(h2u(h0), h2u(h1));
    }
}

// ---------------- fp16 GEMM core (BK=32, 3-stage, 1 barrier/tile) -----------
// C[M,N] = A[M,K] x BT[N,K(ldb)]^T.  BM=BN=128, BK=32, 256 thr, 8 warps 64x32.
#define HSTR 40
#define HSZ  (128 * HSTR)
#define GEMM_SMEM (6 * HSZ * 2)     // 3 stages x (A + B), bytes = 61440

#define GEMM_STAGE(i, st) do {                                                   \
    const int k0_ = (i) << 5;                                                    \
    const __half* ap_ = A + (long long)(bm + (tid >> 1)) * lda + k0_ + (tid & 1) * 16; \
    __half* ad_ = As + (st) * HSZ + (tid >> 1) * HSTR + (tid & 1) * 16;          \
    cp16(ad_, ap_); cp16(ad_ + 8, ap_ + 8);                                      \
    const __half* bp_ = BT + (long long)(bn + (tid >> 1)) * ldb + k0_ + (tid & 1) * 16; \
    __half* bd_ = Bs + (st) * HSZ + (tid >> 1) * HSTR + (tid & 1) * 16;          \
    cp16(bd_, bp_); cp16(bd_ + 8, bp_ + 8);                                      \
} while (0)

#define GEMM_PRE()                                                               \
    extern __shared__ __half smh[];                                              \
    __half* As = smh;                                                            \
    __half* Bs = smh + 3 * HSZ;                                                  \
    const int tid  = threadIdx.x;                                                \
    const int lane = tid & 31;                                                   \
    const int warp = tid >> 5;                                                   \
    const int wm = (warp >> 2) * 64, wn = (warp & 3) * 32;                       \
    const int grp = lane >> 2, tg = lane & 3;                                    \
    const int bm = blockIdx.y * 128, bn = blockIdx.x * 128;                      \
    const int nk = K >> 5;                                                       \
    const uint32_t As_u = (uint32_t)__cvta_generic_to_shared(As);                \
    const uint32_t Bs_u = (uint32_t)__cvta_generic_to_shared(Bs);                \
    const uint32_t a_loff = (uint32_t)(((wm + (lane & 7) + ((lane >> 3) & 1) * 8) * HSTR \
                               + ((lane >> 4) & 1) * 8) * 2);                    \
    const uint32_t b_loff = (uint32_t)(((wn + (lane & 7) + ((lane >> 4) & 1) * 8) * HSTR \
                               + ((lane >> 3) & 1) * 8) * 2);                    \
    float acc[4][4][4];                                                          \
    _Pragma("unroll") for (int i = 0; i < 4; i++)                                \
        _Pragma("unroll") for (int j = 0; j < 4; j++)                            \
            _Pragma("unroll") for (int l = 0; l < 4; l++) acc[i][j][l] = 0.f;

#define GEMM_MAIN()                                                              \
    GEMM_STAGE(0, 0);                                                            \
    CP_COMMIT();                                                                 \
    if (nk > 1) GEMM_STAGE(1, 1);                                                \
    CP_COMMIT();                                                                 \
    for (int i = 0; i < nk; i++) {                                               \
        CP_WAITG(1);              /* stage i resident */                         \
        __syncthreads();          /* + all warps done with buf (i-1)%3 */        \
        if (i + 2 < nk) GEMM_STAGE(i + 2, (i + 2) % 3);                          \
        CP_COMMIT();              /* empty group at tail keeps ordering */       \
        const uint32_t ab = As_u + (uint32_t)((i % 3) * HSZ * 2) + a_loff;       \
        const uint32_t bb = Bs_u + (uint32_t)((i % 3) * HSZ * 2) + b_loff;       \
        _Pragma("unroll")                                                        \
        for (int ks = 0; ks < 32; ks += 16) {                                    \
            uint32_t af[4][4], bfr[4][2];                                        \
            _Pragma("unroll") for (int mi = 0; mi < 4; mi++)                     \
                ldsm4(af[mi][0], af[mi][1], af[mi][2], af[mi][3],                \
                      ab + (uint32_t)((mi * 16 * HSTR + ks) * 2));               \
            ldsm4(bfr[0][0], bfr[0][1], bfr[1][0], bfr[1][1],                    \
                  bb + (uint32_t)(ks * 2));                                      \
            ldsm4(bfr[2][0], bfr[2][1], bfr[3][0], bfr[3][1],                    \
                  bb + (uint32_t)((16 * HSTR + ks) * 2));                        \
            _Pragma("unroll") for (int mi = 0; mi < 4; mi++)                     \
                _Pragma("unroll") for (int ni = 0; ni < 4; ni++)                 \
                    mma_f16(acc[mi][ni], af[mi], bfr[ni]);                       \
        }                                                                        \
    }

// EPI: 2 f32 = acc+bias+res, 3 half = fast_gelu(acc+bias)
template<int EPI>
__global__ __launch_bounds__(256, 2) void gemm_kernel(
    const __half* __restrict__ A, const __half* __restrict__ BT,
    void* __restrict__ Cm, const float* __restrict__ bias, const float* __restrict__ res,
    int M, int N, int K, int lda, int ldb, int ldc)
{
    GEMM_PRE();
    GEMM_MAIN();
    #pragma unroll
    for (int mi = 0; mi < 4; mi++) {
        #pragma unroll
        for (int ni = 0; ni < 4; ni++) {
            int c = bn + wn + ni * 8 + 2 * tg;
            float2 bv = *(const float2*)&bias[c];
            #pragma unroll
            for (int rr2 = 0; rr2 < 2; rr2++) {
                int r = bm + wm + mi * 16 + grp + rr2 * 8;
                float v0 = acc[mi][ni][rr2 * 2], v1 = acc[mi][ni][rr2 * 2 + 1];
                long long off = (long long)r * ldc + c;
                if (EPI == 2) {
                    float* C = (float*)Cm;
                    float2 rv = *(const float2*)&res[off];
                    *(float2*)&C[off] = make_float2(v0 + bv.x + rv.x, v1 + bv.y + rv.y);
                } else {
                    __half* C = (__half*)Cm;
                    *(__half2*)&C[off] =
                        __floats2half2_rn(fast_gelu(v0 + bv.x), fast_gelu(v1 + bv.y));
                }
            }
        }
    }
}

// split-K=2 GEMM: grid.z = 2 K-slices; epilogue accumulates via atomicAdd.
// z==0 contributes acc+bias+res; z==1 contributes acc. C must be pre-zeroed.
__global__ __launch_bounds__(256, 2) void gemm_splitk_kernel(
    const __half* __restrict__ A0, const __half* __restrict__ BT0,
    float* __restrict__ Cm, const float* __restrict__ bias, const float* __restrict__ res,
    int M, int N, int K, int lda, int ldb, int ldc)
{
    const int bz = blockIdx.z;
    const __half* A  = A0  + (long long)bz * K;   // K = slice length
    const __half* BT = BT0 + (long long)bz * K;
    GEMM_PRE();
    GEMM_MAIN();
    #pragma unroll
    for (int mi = 0; mi < 4; mi++) {
        #pragma unroll
        for (int ni = 0; ni < 4; ni++) {
            int c = bn + wn + ni * 8 + 2 * tg;
            float2 bv = *(const float2*)&bias[c];
            #pragma unroll
            for (int rr2 = 0; rr2 < 2; rr2++) {
                int r = bm + wm + mi * 16 + grp + rr2 * 8;
                float v0 = acc[mi][ni][rr2 * 2], v1 = acc[mi][ni][rr2 * 2 + 1];
                long long off = (long long)r * ldc + c;
                if (bz == 0) {
                    float2 rv = *(const float2*)&res[off];
                    atomicAdd(&Cm[off],     v0 + bv.x + rv.x);
                    atomicAdd(&Cm[off + 1], v1 + bv.y + rv.y);
                } else {
                    atomicAdd(&Cm[off],     v0);
                    atomicAdd(&Cm[off + 1], v1);
                }
            }
        }
    }
}

// qkv GEMM: scatter epilogue -> q (scaled 1/8), k, v-transposed
__global__ __launch_bounds__(256, 2) void qkv_gemm_kernel(
    const __half* __restrict__ A, const __half* __restrict__ BT,
    __half* __restrict__ gq, __half* __restrict__ gk, __half* __restrict__ gvt,
    int M, int N, int K, int lda, int ldb)
{
    GEMM_PRE();
    GEMM_MAIN();
    #pragma unroll
    for (int mi = 0; mi < 4; mi++) {
        #pragma unroll
        for (int ni = 0; ni < 4; ni++) {
            int c = bn + wn + ni * 8 + 2 * tg;
            if (c >= 192) continue;
            #pragma unroll
            for (int rr2 = 0; rr2 < 2; rr2++) {
                int r = bm + wm + mi * 16 + grp + rr2 * 8;
                float v0 = acc[mi][ni][rr2 * 2], v1 = acc[mi][ni][rr2 * 2 + 1];
                if (c < 64) {
                    *(__half2*)&gq[(long long)r * 64 + c] =
                        __floats2half2_rn(v0 * 0.125f, v1 * 0.125f);
                } else if (c < 128) {
                    *(__half2*)&gk[(long long)r * 64 + (c - 64)] = __floats2half2_rn(v0, v1);
                } else {
                    int d = c - 128, bt = r >> 11, s = r & 2047;
                    gvt[((long long)(bt * 64 + d)) * 2048 + s]     = __float2half(v0);
                    gvt[((long long)(bt * 64 + d + 1)) * 2048 + s] = __float2half(v1);
                }
            }
        }
    }
}

// ---------------- flash attention (fp16, 3-stage KV, 1 barrier/tile) --------
#define FST 72
#define FLASH_SMEM (7 * 64 * FST * 2)    // Q + 3K + 3V

__global__ __launch_bounds__(128, 2) void flash_kernel(
    const __half* __restrict__ gq, const __half* __restrict__ gk,
    const __half* __restrict__ gvt, __half* __restrict__ oh)
{
    extern __shared__ __half smh[];
    __half* Qs = smh;                      // [64][72]
    __half* Ks = smh + 64 * FST;           // 3 x [64][72]
    __half* Vs = Ks + 3 * 64 * FST;        // 3 x [64][72]  (rows = d, cols = kv)

    const int tid = threadIdx.x, lane = tid & 31, warp = tid >> 5;
    const int grp = lane >> 2, tg = lane & 3;
    const int qt = blockIdx.x, batch = blockIdx.y;
    const long long rowbase = (long long)batch * SS;

    const int rid = tid >> 1, sel = tid & 1;

    const uint32_t Ks_u = (uint32_t)__cvta_generic_to_shared(Ks);
    const uint32_t Vs_u = (uint32_t)__cvta_generic_to_shared(Vs);
    const uint32_t kv_loff = (uint32_t)((((lane & 7) + ((lane >> 4) & 1) * 8) * FST
                               + ((lane >> 3) & 1) * 8) * 2);

    auto stage_kv = [&](int t, int st) {
        const __half* kp = gk + (rowbase + t * 64 + rid) * 64 + sel * 32;
        __half* kd = Ks + st * 64 * FST + rid * FST + sel * 32;
        cp16(kd, kp); cp16(kd + 8, kp + 8); cp16(kd + 16, kp + 16); cp16(kd + 24, kp + 24);
        const __half* vp = gvt + ((long long)(batch * 64 + rid)) * 2048 + t * 64 + sel * 32;
        __half* vd = Vs + st * 64 * FST + rid * FST + sel * 32;
        cp16(vd, vp); cp16(vd + 8, vp + 8); cp16(vd + 16, vp + 16); cp16(vd + 24, vp + 24);
    };

    {
        const __half* qp = gq + (rowbase + qt * 64 + rid) * 64 + sel * 32;
        __half* qd = Qs + rid * FST + sel * 32;
        cp16(qd, qp); cp16(qd + 8, qp + 8); cp16(qd + 16, qp + 16); cp16(qd + 24, qp + 24);
    }
    stage_kv(0, 0);
    CP_COMMIT();
    stage_kv(1, 1);
    CP_COMMIT();

    CP_WAITG(1);            // group 0 (Q + kv0) resident
    __syncthreads();

    uint32_t qf[4][4];
    {
        const uint32_t Qs_u = (uint32_t)__cvta_generic_to_shared(Qs);
        const uint32_t q_loff = (uint32_t)(((warp * 16 + (lane & 7) + ((lane >> 3) & 1) * 8) * FST
                                 + ((lane >> 4) & 1) * 8) * 2);
        #pragma unroll
        for (int kc = 0; kc < 4; kc++)
            ldsm4(qf[kc][0], qf[kc][1], qf[kc][2], qf[kc][3],
                  Qs_u + q_loff + (uint32_t)(kc * 16 * 2));
    }

    float m0 = -1e30f, m1 = -1e30f, l0 = 0.f, l1 = 0.f;
    float oacc[8][4];
    #pragma unroll
    for (int i = 0; i < 8; i++)
        #pragma unroll
        for (int j = 0; j < 4; j++) oacc[i][j] = 0.f;

    for (int t = 0; t < 32; t++) {
        if (t + 2 < 32) stage_kv(t + 2, (t + 2) % 3);
        CP_COMMIT();

        const uint32_t Kb = Ks_u + (uint32_t)((t % 3) * 64 * FST * 2) + kv_loff;
        const uint32_t Vb = Vs_u + (uint32_t)((t % 3) * 64 * FST * 2) + kv_loff;

        float sacc[8][4];
        #pragma unroll
        for (int i = 0; i < 8; i++)
            #pragma unroll
            for (int j = 0; j < 4; j++) sacc[i][j] = 0.f;

        #pragma unroll
        for (int kc = 0; kc < 4; kc++) {
            uint32_t kb[8][2];
            #pragma unroll
            for (int nb = 0; nb < 4; nb++)
                ldsm4(kb[2 * nb][0], kb[2 * nb][1], kb[2 * nb + 1][0], kb[2 * nb + 1][1],
                      Kb + (uint32_t)((nb * 16 * FST + kc * 16) * 2));
            #pragma unroll
            for (int ni = 0; ni < 8; ni++)
                mma_f16(sacc[ni], qf[kc], kb[ni]);
        }

        float mt0 = -1e30f, mt1 = -1e30f;
        #pragma unroll
        for (int ni = 0; ni < 8; ni++) {
            mt0 = fmaxf(mt0, fmaxf(sacc[ni][0], sacc[ni][1]));
            mt1 = fmaxf(mt1, fmaxf(sacc[ni][2], sacc[ni][3]));
        }
        mt0 = fmaxf(mt0, __shfl_xor_sync(0xffffffffu, mt0, 1));
        mt0 = fmaxf(mt0, __shfl_xor_sync(0xffffffffu, mt0, 2));
        mt1 = fmaxf(mt1, __shfl_xor_sync(0xffffffffu, mt1, 1));
        mt1 = fmaxf(mt1, __shfl_xor_sync(0xffffffffu, mt1, 2));
        float mn0 = fmaxf(m0, mt0), mn1 = fmaxf(m1, mt1);
        float a0 = __expf(m0 - mn0), a1 = __expf(m1 - mn1);
        float ps0 = 0.f, ps1 = 0.f;
        #pragma unroll
        for (int ni = 0; ni < 8; ni++) {
            sacc[ni][0] = __expf(sacc[ni][0] - mn0); ps0 += sacc[ni][0];
            sacc[ni][1] = __expf(sacc[ni][1] - mn0); ps0 += sacc[ni][1];
            sacc[ni][2] = __expf(sacc[ni][2] - mn1); ps1 += sacc[ni][2];
            sacc[ni][3] = __expf(sacc[ni][3] - mn1); ps1 += sacc[ni][3];
        }
        ps0 += __shfl_xor_sync(0xffffffffu, ps0, 1);
        ps0 += __shfl_xor_sync(0xffffffffu, ps0, 2);
        ps1 += __shfl_xor_sync(0xffffffffu, ps1, 1);
        ps1 += __shfl_xor_sync(0xffffffffu, ps1, 2);
        l0 = l0 * a0 + ps0; l1 = l1 * a1 + ps1;
        m0 = mn0; m1 = mn1;
        #pragma unroll
        for (int dn = 0; dn < 8; dn++) {
            oacc[dn][0] *= a0; oacc[dn][1] *= a0;
            oacc[dn][2] *= a1; oacc[dn][3] *= a1;
        }

        #pragma unroll
        for (int kc = 0; kc < 4; kc++) {
            uint32_t af[4];
            af[0] = h2u(__floats2half2_rn(sacc[2 * kc][0],     sacc[2 * kc][1]));
            af[1] = h2u(__floats2half2_rn(sacc[2 * kc][2],     sacc[2 * kc][3]));
            af[2] = h2u(__floats2half2_rn(sacc[2 * kc + 1][0], sacc[2 * kc + 1][1]));
            af[3] = h2u(__floats2half2_rn(sacc[2 * kc + 1][2], sacc[2 * kc + 1][3]));
            uint32_t vb[8][2];
            #pragma unroll
            for (int nb = 0; nb < 4; nb++)
                ldsm4(vb[2 * nb][0], vb[2 * nb][1], vb[2 * nb + 1][0], vb[2 * nb + 1][1],
                      Vb + (uint32_t)((nb * 16 * FST + kc * 16) * 2));
            #pragma unroll
            for (int dn = 0; dn < 8; dn++)
                mma_f16(oacc[dn], af, vb[dn]);
        }

        __syncthreads();       // all warps done reading buf t%3
        CP_WAITG(1);           // tile t+1 resident for next iteration
    }

    float i0 = 1.f / l0, i1 = 1.f / l1;
    int r0 = qt * 64 + warp * 16 + grp;
    __half* d0 = oh + (rowbase + r0) * DQ;
    __half* d1 = oh + (rowbase + r0 + 8) * DQ;
    #pragma unroll
    for (int dn = 0; dn < 8; dn++) {
        int col = dn * 8 + 2 * tg;
        *(__half2*)(d0 + col) = __floats2half2_rn(oacc[dn][0] * i0, oacc[dn][1] * i0);
        *(__half2*)(d1 + col) = __floats2half2_rn(oacc[dn][2] * i1, oacc[dn][3] * i1);
    }
}

// ---------------- launch ----------------------------------------------------
extern "C" void kernel_launch(void* const* d_in, const int* in_sizes, int n_in,
                              void* d_out, int out_size) {
    const float* x    = (const float*)d_in[0];
    const float* wq   = (const float*)d_in[1];
    const float* wk   = (const float*)d_in[2];
    const float* wv   = (const float*)d_in[3];
    const float* linw = (const float*)d_in[4];
    const float* linb = (const float*)d_in[5];
    const float* ln1g = (const float*)d_in[6];
    const float* ln1b = (const float*)d_in[7];
    const float* f1w  = (const float*)d_in[8];
    const float* f1b  = (const float*)d_in[9];
    const float* f2w  = (const float*)d_in[10];
    const float* f2b  = (const float*)d_in[11];
    float* out = (float*)d_out;

    void *p_h, *p_h2, *p_y1, *p_q, *p_k, *p_vt, *p_oh, *p_a1;
    void *p_wsT, *p_wqkvT, *p_f1T, *p_f2T;
    cudaGetSymbolAddress(&p_h,     g_h);
    cudaGetSymbolAddress(&p_h2,    g_h2);
    cudaGetSymbolAddress(&p_y1,    g_y1);
    cudaGetSymbolAddress(&p_q,     g_q);
    cudaGetSymbolAddress(&p_k,     g_k);
    cudaGetSymbolAddress(&p_vt,    g_vt);
    cudaGetSymbolAddress(&p_oh,    g_oh);
    cudaGetSymbolAddress(&p_a1,    g_a1);
    cudaGetSymbolAddress(&p_wsT,   g_wsT);
    cudaGetSymbolAddress(&p_wqkvT, g_wqkvT);
    cudaGetSymbolAddress(&p_f1T,   g_f1T);
    cudaGetSymbolAddress(&p_f2T,   g_f2T);

    cudaFuncSetAttribute(gemm_kernel<2>,     cudaFuncAttributeMaxDynamicSharedMemorySize, GEMM_SMEM);
    cudaFuncSetAttribute(gemm_kernel<3>,     cudaFuncAttributeMaxDynamicSharedMemorySize, GEMM_SMEM);
    cudaFuncSetAttribute(gemm_splitk_kernel, cudaFuncAttributeMaxDynamicSharedMemorySize, GEMM_SMEM);
    cudaFuncSetAttribute(qkv_gemm_kernel,    cudaFuncAttributeMaxDynamicSharedMemorySize, GEMM_SMEM);
    cudaFuncSetAttribute(flash_kernel,       cudaFuncAttributeMaxDynamicSharedMemorySize, FLASH_SMEM);

    #define HP(p) ((__half*)(p))
    #define FP(p) ((float*)(p))

    wsumT_kernel<<<dim3(2, 24), dim3(32, 8)>>>(linw, HP(p_wsT));
    pack_wqkvT_kernel<<<dim3(8, 24), dim3(32, 8)>>>(wq, wk, wv, HP(p_wqkvT));
    transposeh_kernel<<<dim3(HH / 32, DD / 32), dim3(32, 8)>>>(f1w, HP(p_f1T), DD, HH);
    transposeh_kernel<<<dim3(DD / 32, HH / 32), dim3(32, 8)>>>(f2w, HP(p_f2T), HH, DD);

    // LN1: x -> h (half), warp-per-row
    ln_kernel<<<RR / 8, 256>>>(x, ln1g, ln1b, HP(p_h));

    // qkv: h @ wqkv -> q (1/8), k, v^T
    qkv_gemm_kernel<<<dim3(2, 64), 256, GEMM_SMEM>>>(HP(p_h), HP(p_wqkvT),
        HP(p_q), HP(p_k), HP(p_vt), RR, 256, DD, DD, DD);

    // flash attention -> oh (half)
    flash_kernel<<<dim3(32, 4), 128, FLASH_SMEM>>>(HP(p_q), HP(p_k), HP(p_vt), HP(p_oh));

    // y1 = oh @ Ws + lin_b + x  (fp32)
    gemm_kernel<2><<<dim3(6, 64), 256, GEMM_SMEM>>>(HP(p_oh), HP(p_wsT), p_y1,
        linb, x, RR, DD, DQ, DQ, DQ, DD);

    // LN2 (reuses ln1 params, matching reference): y1 -> h2 (half)
    ln_kernel<<<RR / 8, 256>>>(FP(p_y1), ln1g, ln1b, HP(p_h2));

    // a1 = gelu(h2 @ fc1 + b1)  (half)
    gemm_kernel<3><<<dim3(24, 64), 256, GEMM_SMEM>>>(HP(p_h2), HP(p_f1T), p_a1,
        f1b, nullptr, RR, HH, DD, DD, DD, HH);

    // out = a1 @ fc2 + b2 + y1  (fp32), split-K=2 with atomic accumulation
    zero_kernel<<<(RR * DD / 4 + 255) / 256, 256>>>((float4*)out, RR * DD / 4);
    gemm_splitk_kernel<<<dim3(6, 64, 2), 256, GEMM_SMEM>>>(HP(p_a1), HP(p_f2T), out,
        f2b, FP(p_y1), RR, DD, HH / 2, HH, HH, DD);
    #undef HP
    #undef FP
}

// round 15
// speedup vs baseline: 1.0082x; 1.0082x over previous
#include <cuda_runtime.h>
#include <cuda_fp16.h>
#include <stdint.h>

// Problem dims
#define BB 4
#define SS 2048
#define DD 768
#define DQ 64
#define HH 3072
#define RR 8192   // BB*SS

// ---------------- scratch (device globals; no allocation allowed) ----------
__device__ __half g_h    [RR*DD];
__device__ __half g_h2   [RR*DD];
__device__ float  g_y1   [RR*DD];
__device__ __half g_q    [RR*DQ];          // pre-scaled by 1/8
__device__ __half g_k    [RR*DQ];
__device__ __half g_vt   [BB*DQ*SS];       // [batch][d][s]  (V transposed)
__device__ __half g_oh   [RR*DQ];
__device__ float  g_op   [2*RR*DQ];        // split-KV partial O (unnormalized)
__device__ float2 g_ml   [2*RR];           // split-KV (m, l) per row per half
__device__ __half g_a1   [(long long)RR*HH];
__device__ __half g_wsT  [DD*DQ];          // [n=768][k=64]
__device__ __half g_wqkvT[256*DD];         // [n=256][k=768]
__device__ __half g_f1T  [HH*DD];          // [3072][768]
__device__ __half g_f2T  [DD*HH];          // [768][3072]

__device__ __forceinline__ void cp16(void* dst, const void* src) {
    uint32_t d = (uint32_t)__cvta_generic_to_shared(dst);
    asm volatile("cp.async.cg.shared.global [%0], [%1], 16;\n" :: "r"(d), "l"(src));
}
#define CP_COMMIT() asm volatile("cp.async.commit_group;\n" ::: "memory")
#define CP_WAITG(n) asm volatile("cp.async.wait_group %0;\n" :: "n"(n) : "memory")

__device__ __forceinline__ void mma_f16(float* c, const uint32_t* a, const uint32_t* b) {
    asm volatile(
        "mma.sync.aligned.m16n8k16.row.col.f32.f16.f16.f32 "
        "{%0,%1,%2,%3}, {%4,%5,%6,%7}, {%8,%9}, {%0,%1,%2,%3};\n"
        : "+f"(c[0]), "+f"(c[1]), "+f"(c[2]), "+f"(c[3])
        : "r"(a[0]), "r"(a[1]), "r"(a[2]), "r"(a[3]), "r"(b[0]), "r"(b[1]));
}

__device__ __forceinline__ void ldsm4(uint32_t& r0, uint32_t& r1, uint32_t& r2, uint32_t& r3,
                                      uint32_t a) {
    asm volatile("ldmatrix.sync.aligned.m8n8.x4.shared.b16 {%0,%1,%2,%3}, [%4];"
        : "=r"(r0), "=r"(r1), "=r"(r2), "=r"(r3) : "r"(a));
}

__device__ __forceinline__ uint32_t h2u(__half2 h) {
    return *reinterpret_cast<uint32_t*>(&h);
}

// fast erf-based GELU: Abramowitz-Stegun 7.1.26, |abs err| < 1.5e-7
__device__ __forceinline__ float fast_gelu(float x) {
    float z  = 0.70710678118654752f * x;
    float az = fabsf(z);
    float t  = __fdividef(1.0f, 1.0f + 0.3275911f * az);
    float e  = __expf(-az * az);
    float poly = ((((1.061405429f * t - 1.453152027f) * t + 1.421413741f) * t
                 - 0.284496736f) * t + 0.254829592f) * t;
    float erfv = copysignf(1.0f - poly * e, x);
    return 0.5f * x * (1.0f + erfv);
}

// ---------------- prologue kernels -----------------------------------------
// WsT[n][k] = half( sum_h lin_w[h*64+k][n] ), tiled transpose (coalesced)
__global__ void wsumT_kernel(const float* __restrict__ w, __half* __restrict__ d) {
    __shared__ float t[32][33];
    int kb = blockIdx.x * 32, nb = blockIdx.y * 32;
    int tx = threadIdx.x, ty = threadIdx.y;
    #pragma unroll
    for (int j = 0; j < 32; j += 8) {
        int k = kb + ty + j, n = nb + tx;
        float s = 0.f;
        #pragma unroll
        for (int h = 0; h < 12; h++) s += w[(h * DQ + k) * DD + n];
        t[ty + j][tx] = s;
    }
    __syncthreads();
    #pragma unroll
    for (int j = 0; j < 32; j += 8)
        d[(nb + ty + j) * DQ + kb + tx] = __float2half(t[tx][ty + j]);
}

// wqkvT[c][r] tiled transpose, c: q|k|v|zero-pad
__global__ void pack_wqkvT_kernel(const float* __restrict__ wq, const float* __restrict__ wk,
                                  const float* __restrict__ wv, __half* __restrict__ d) {
    __shared__ float t[32][33];
    int cb = blockIdx.x * 32, rb = blockIdx.y * 32;
    int tx = threadIdx.x, ty = threadIdx.y;
    const float* src = nullptr; int c0 = 0;
    if (cb < 64)       { src = wq; c0 = cb; }
    else if (cb < 128) { src = wk; c0 = cb - 64; }
    else if (cb < 192) { src = wv; c0 = cb - 128; }
    #pragma unroll
    for (int j = 0; j < 32; j += 8)
        t[ty + j][tx] = src ? src[(rb + ty + j) * DQ + c0 + tx] : 0.f;
    __syncthreads();
    #pragma unroll
    for (int j = 0; j < 32; j += 8)
        d[(long long)(cb + ty + j) * DD + rb + tx] = __float2half(t[tx][ty + j]);
}

__global__ void transposeh_kernel(const float* __restrict__ in, __half* __restrict__ out,
                                  int K, int N) {
    __shared__ float t[32][33];
    int nb = blockIdx.x * 32, kb = blockIdx.y * 32;
    int tx = threadIdx.x, ty = threadIdx.y;
    #pragma unroll
    for (int j = 0; j < 32; j += 8)
        t[ty + j][tx] = in[(long long)(kb + ty + j) * N + nb + tx];
    __syncthreads();
    #pragma unroll
    for (int j = 0; j < 32; j += 8)
        out[(long long)(nb + ty + j) * K + kb + tx] = __float2half(t[tx][ty + j]);
}

// LayerNorm: warp-per-row, float4, shfl-only reduction, no __syncthreads.
__global__ __launch_bounds__(256) void ln_kernel(
    const float* __restrict__ x, const float* __restrict__ g,
    const float* __restrict__ b, __half* __restrict__ o)
{
    const int warp = threadIdx.x >> 5, lane = threadIdx.x & 31;
    const long long row = (long long)blockIdx.x * 8 + warp;
    const float4* xr = (const float4*)(x + row * DD);
    float4 v[6];
    float s1 = 0.f, s2 = 0.f;
    #pragma unroll
    for (int j = 0; j < 6; j++) {
        v[j] = xr[lane + 32 * j];
        s1 += v[j].x + v[j].y + v[j].z + v[j].w;
        s2 += v[j].x * v[j].x + v[j].y * v[j].y + v[j].z * v[j].z + v[j].w * v[j].w;
    }
    #pragma unroll
    for (int off = 16; off; off >>= 1) {
        s1 += __shfl_xor_sync(0xffffffffu, s1, off);
        s2 += __shfl_xor_sync(0xffffffffu, s2, off);
    }
    float mu = s1 * (1.f / 768.f);
    float var = s2 * (1.f / 768.f) - mu * mu;
    float rs = rsqrtf(var + 1e-5f);
    const float4* gr = (const float4*)g;
    const float4* br = (const float4*)b;
    uint2* orow = (uint2*)(o + row * DD);
    #pragma unroll
    for (int j = 0; j < 6; j++) {
        float4 gv = gr[lane + 32 * j], bv = br[lane + 32 * j];
        __half2 h0 = __floats2half2_rn((v[j].x - mu) * rs * gv.x + bv.x,
                                       (v[j].y - mu) * rs * gv.y + bv.y);
        __half2 h1 = __floats2half2_rn((v[j].z - mu) * rs * gv.z + bv.z,
                                       (v[j].w - mu) * rs * gv.w + bv.w);
        orow[lane + 32 * j] = make_uint2(h2u(h0), h2u(h1));
    }
}

// ---------------- fp16 GEMM core (BK=32, 3-stage, 1 barrier/tile) -----------
// C[M,N] = A[M,K] x BT[N,K(ldb)]^T.  BM=BN=128, BK=32, 256 thr, 8 warps 64x32.
#define HSTR 40
#define HSZ  (128 * HSTR)
#define GEMM_SMEM (6 * HSZ * 2)     // 3 stages x (A + B), bytes = 61440

#define GEMM_STAGE(i, st) do {                                                   \
    const int k0_ = (i) << 5;                                                    \
    const __half* ap_ = A + (long long)(bm + (tid >> 1)) * lda + k0_ + (tid & 1) * 16; \
    __half* ad_ = As + (st) * HSZ + (tid >> 1) * HSTR + (tid & 1) * 16;          \
    cp16(ad_, ap_); cp16(ad_ + 8, ap_ + 8);                                      \
    const __half* bp_ = BT + (long long)(bn + (tid >> 1)) * ldb + k0_ + (tid & 1) * 16; \
    __half* bd_ = Bs + (st) * HSZ + (tid >> 1) * HSTR + (tid & 1) * 16;          \
    cp16(bd_, bp_); cp16(bd_ + 8, bp_ + 8);                                      \
} while (0)

#define GEMM_PRE()                                                               \
    extern __shared__ __half smh[];                                              \
    __half* As = smh;                                                            \
    __half* Bs = smh + 3 * HSZ;                                                  \
    const int tid  = threadIdx.x;                                                \
    const int lane = tid & 31;                                                   \
    const int warp = tid >> 5;                                                   \
    const int wm = (warp >> 2) * 64, wn = (warp & 3) * 32;                       \
    const int grp = lane >> 2, tg = lane & 3;                                    \
    const int bm = blockIdx.y * 128, bn = blockIdx.x * 128;                      \
    const int nk = K >> 5;                                                       \
    const uint32_t As_u = (uint32_t)__cvta_generic_to_shared(As);                \
    const uint32_t Bs_u = (uint32_t)__cvta_generic_to_shared(Bs);                \
    const uint32_t a_loff = (uint32_t)(((wm + (lane & 7) + ((lane >> 3) & 1) * 8) * HSTR \
                               + ((lane >> 4) & 1) * 8) * 2);                    \
    const uint32_t b_loff = (uint32_t)(((wn + (lane & 7) + ((lane >> 4) & 1) * 8) * HSTR \
                               + ((lane >> 3) & 1) * 8) * 2);                    \
    float acc[4][4][4];                                                          \
    _Pragma("unroll") for (int i = 0; i < 4; i++)                                \
        _Pragma("unroll") for (int j = 0; j < 4; j++)                            \
            _Pragma("unroll") for (int l = 0; l < 4; l++) acc[i][j][l] = 0.f;

#define GEMM_MAIN()                                                              \
    GEMM_STAGE(0, 0);                                                            \
    CP_COMMIT();                                                                 \
    if (nk > 1) GEMM_STAGE(1, 1);                                                \
    CP_COMMIT();                                                                 \
    for (int i = 0; i < nk; i++) {                                               \
        CP_WAITG(1);              /* stage i resident */                         \
        __syncthreads();          /* + all warps done with buf (i-1)%3 */        \
        if (i + 2 < nk) GEMM_STAGE(i + 2, (i + 2) % 3);                          \
        CP_COMMIT();              /* empty group at tail keeps ordering */       \
        const uint32_t ab = As_u + (uint32_t)((i % 3) * HSZ * 2) + a_loff;       \
        const uint32_t bb = Bs_u + (uint32_t)((i % 3) * HSZ * 2) + b_loff;       \
        _Pragma("unroll")                                                        \
        for (int ks = 0; ks < 32; ks += 16) {                                    \
            uint32_t af[4][4], bfr[4][2];                                        \
            _Pragma("unroll") for (int mi = 0; mi < 4; mi++)                     \
                ldsm4(af[mi][0], af[mi][1], af[mi][2], af[mi][3],                \
                      ab + (uint32_t)((mi * 16 * HSTR + ks) * 2));               \
            ldsm4(bfr[0][0], bfr[0][1], bfr[1][0], bfr[1][1],                    \
                  bb + (uint32_t)(ks * 2));                                      \
            ldsm4(bfr[2][0], bfr[2][1], bfr[3][0], bfr[3][1],                    \
                  bb + (uint32_t)((16 * HSTR + ks) * 2));                        \
            _Pragma("unroll") for (int mi = 0; mi < 4; mi++)                     \
                _Pragma("unroll") for (int ni = 0; ni < 4; ni++)                 \
                    mma_f16(acc[mi][ni], af[mi], bfr[ni]);                       \
        }                                                                        \
    }

// EPI: 2 f32 = acc+bias+res, 3 half = fast_gelu(acc+bias)
template<int EPI>
__global__ __launch_bounds__(256, 2) void gemm_kernel(
    const __half* __restrict__ A, const __half* __restrict__ BT,
    void* __restrict__ Cm, const float* __restrict__ bias, const float* __restrict__ res,
    int M, int N, int K, int lda, int ldb, int ldc)
{
    GEMM_PRE();
    GEMM_MAIN();
    #pragma unroll
    for (int mi = 0; mi < 4; mi++) {
        #pragma unroll
        for (int ni = 0; ni < 4; ni++) {
            int c = bn + wn + ni * 8 + 2 * tg;
            float2 bv = *(const float2*)&bias[c];
            #pragma unroll
            for (int rr2 = 0; rr2 < 2; rr2++) {
                int r = bm + wm + mi * 16 + grp + rr2 * 8;
                float v0 = acc[mi][ni][rr2 * 2], v1 = acc[mi][ni][rr2 * 2 + 1];
                long long off = (long long)r * ldc + c;
                if (EPI == 2) {
                    float* C = (float*)Cm;
                    float2 rv = *(const float2*)&res[off];
                    *(float2*)&C[off] = make_float2(v0 + bv.x + rv.x, v1 + bv.y + rv.y);
                } else {
                    __half* C = (__half*)Cm;
                    *(__half2*)&C[off] =
                        __floats2half2_rn(fast_gelu(v0 + bv.x), fast_gelu(v1 + bv.y));
                }
            }
        }
    }
}

// qkv GEMM: scatter epilogue -> q (scaled 1/8), k, v-transposed
__global__ __launch_bounds__(256, 2) void qkv_gemm_kernel(
    const __half* __restrict__ A, const __half* __restrict__ BT,
    __half* __restrict__ gq, __half* __restrict__ gk, __half* __restrict__ gvt,
    int M, int N, int K, int lda, int ldb)
{
    GEMM_PRE();
    GEMM_MAIN();
    #pragma unroll
    for (int mi = 0; mi < 4; mi++) {
        #pragma unroll
        for (int ni = 0; ni < 4; ni++) {
            int c = bn + wn + ni * 8 + 2 * tg;
            if (c >= 192) continue;
            #pragma unroll
            for (int rr2 = 0; rr2 < 2; rr2++) {
                int r = bm + wm + mi * 16 + grp + rr2 * 8;
                float v0 = acc[mi][ni][rr2 * 2], v1 = acc[mi][ni][rr2 * 2 + 1];
                if (c < 64) {
                    *(__half2*)&gq[(long long)r * 64 + c] =
                        __floats2half2_rn(v0 * 0.125f, v1 * 0.125f);
                } else if (c < 128) {
                    *(__half2*)&gk[(long long)r * 64 + (c - 64)] = __floats2half2_rn(v0, v1);
                } else {
                    int d = c - 128, bt = r >> 11, s = r & 2047;
                    gvt[((long long)(bt * 64 + d)) * 2048 + s]     = __float2half(v0);
                    gvt[((long long)(bt * 64 + d + 1)) * 2048 + s] = __float2half(v1);
                }
            }
        }
    }
}

// ---------------- flash attention: split-KV=2, 3-stage KV pipeline ----------
// grid (32 q-tiles, 4 batches, 2 kv-halves). Each half does 16 KV tiles and
// writes unnormalized partial O (fp32) + per-row (m, l).
#define FST 72
#define FLASH_SMEM (7 * 64 * FST * 2)    // Q + 3K + 3V

__global__ __launch_bounds__(128, 2) void flash_kernel(
    const __half* __restrict__ gq, const __half* __restrict__ gk,
    const __half* __restrict__ gvt, float* __restrict__ op, float2* __restrict__ ml)
{
    extern __shared__ __half smh[];
    __half* Qs = smh;                      // [64][72]
    __half* Ks = smh + 64 * FST;           // 3 x [64][72]
    __half* Vs = Ks + 3 * 64 * FST;        // 3 x [64][72]  (rows = d, cols = kv)

    const int tid = threadIdx.x, lane = tid & 31, warp = tid >> 5;
    const int grp = lane >> 2, tg = lane & 3;
    const int qt = blockIdx.x, batch = blockIdx.y, half = blockIdx.z;
    const int t0 = half * 16;
    const long long rowbase = (long long)batch * SS;

    const int rid = tid >> 1, sel = tid & 1;

    const uint32_t Ks_u = (uint32_t)__cvta_generic_to_shared(Ks);
    const uint32_t Vs_u = (uint32_t)__cvta_generic_to_shared(Vs);
    const uint32_t kv_loff = (uint32_t)((((lane & 7) + ((lane >> 4) & 1) * 8) * FST
                               + ((lane >> 3) & 1) * 8) * 2);

    auto stage_kv = [&](int t, int st) {
        const __half* kp = gk + (rowbase + t * 64 + rid) * 64 + sel * 32;
        __half* kd = Ks + st * 64 * FST + rid * FST + sel * 32;
        cp16(kd, kp); cp16(kd + 8, kp + 8); cp16(kd + 16, kp + 16); cp16(kd + 24, kp + 24);
        const __half* vp = gvt + ((long long)(batch * 64 + rid)) * 2048 + t * 64 + sel * 32;
        __half* vd = Vs + st * 64 * FST + rid * FST + sel * 32;
        cp16(vd, vp); cp16(vd + 8, vp + 8); cp16(vd + 16, vp + 16); cp16(vd + 24, vp + 24);
    };

    {
        const __half* qp = gq + (rowbase + qt * 64 + rid) * 64 + sel * 32;
        __half* qd = Qs + rid * FST + sel * 32;
        cp16(qd, qp); cp16(qd + 8, qp + 8); cp16(qd + 16, qp + 16); cp16(qd + 24, qp + 24);
    }
    stage_kv(t0, 0);
    CP_COMMIT();
    stage_kv(t0 + 1, 1);
    CP_COMMIT();

    CP_WAITG(1);            // group 0 (Q + kv0) resident
    __syncthreads();

    uint32_t qf[4][4];
    {
        const uint32_t Qs_u = (uint32_t)__cvta_generic_to_shared(Qs);
        const uint32_t q_loff = (uint32_t)(((warp * 16 + (lane & 7) + ((lane >> 3) & 1) * 8) * FST
                                 + ((lane >> 4) & 1) * 8) * 2);
        #pragma unroll
        for (int kc = 0; kc < 4; kc++)
            ldsm4(qf[kc][0], qf[kc][1], qf[kc][2], qf[kc][3],
                  Qs_u + q_loff + (uint32_t)(kc * 16 * 2));
    }

    float m0 = -1e30f, m1 = -1e30f, l0 = 0.f, l1 = 0.f;
    float oacc[8][4];
    #pragma unroll
    for (int i = 0; i < 8; i++)
        #pragma unroll
        for (int j = 0; j < 4; j++) oacc[i][j] = 0.f;

    for (int tt = 0; tt < 16; tt++) {
        if (tt + 2 < 16) stage_kv(t0 + tt + 2, (tt + 2) % 3);
        CP_COMMIT();

        const uint32_t Kb = Ks_u + (uint32_t)((tt % 3) * 64 * FST * 2) + kv_loff;
        const uint32_t Vb = Vs_u + (uint32_t)((tt % 3) * 64 * FST * 2) + kv_loff;

        float sacc[8][4];
        #pragma unroll
        for (int i = 0; i < 8; i++)
            #pragma unroll
            for (int j = 0; j < 4; j++) sacc[i][j] = 0.f;

        #pragma unroll
        for (int kc = 0; kc < 4; kc++) {
            uint32_t kb[8][2];
            #pragma unroll
            for (int nb = 0; nb < 4; nb++)
                ldsm4(kb[2 * nb][0], kb[2 * nb][1], kb[2 * nb + 1][0], kb[2 * nb + 1][1],
                      Kb + (uint32_t)((nb * 16 * FST + kc * 16) * 2));
            #pragma unroll
            for (int ni = 0; ni < 8; ni++)
                mma_f16(sacc[ni], qf[kc], kb[ni]);
        }

        float mt0 = -1e30f, mt1 = -1e30f;
        #pragma unroll
        for (int ni = 0; ni < 8; ni++) {
            mt0 = fmaxf(mt0, fmaxf(sacc[ni][0], sacc[ni][1]));
            mt1 = fmaxf(mt1, fmaxf(sacc[ni][2], sacc[ni][3]));
        }
        mt0 = fmaxf(mt0, __shfl_xor_sync(0xffffffffu, mt0, 1));
        mt0 = fmaxf(mt0, __shfl_xor_sync(0xffffffffu, mt0, 2));
        mt1 = fmaxf(mt1, __shfl_xor_sync(0xffffffffu, mt1, 1));
        mt1 = fmaxf(mt1, __shfl_xor_sync(0xffffffffu, mt1, 2));
        float mn0 = fmaxf(m0, mt0), mn1 = fmaxf(m1, mt1);
        float a0 = __expf(m0 - mn0), a1 = __expf(m1 - mn1);
        float ps0 = 0.f, ps1 = 0.f;
        #pragma unroll
        for (int ni = 0; ni < 8; ni++) {
            sacc[ni][0] = __expf(sacc[ni][0] - mn0); ps0 += sacc[ni][0];
            sacc[ni][1] = __expf(sacc[ni][1] - mn0); ps0 += sacc[ni][1];
            sacc[ni][2] = __expf(sacc[ni][2] - mn1); ps1 += sacc[ni][2];
            sacc[ni][3] = __expf(sacc[ni][3] - mn1); ps1 += sacc[ni][3];
        }
        ps0 += __shfl_xor_sync(0xffffffffu, ps0, 1);
        ps0 += __shfl_xor_sync(0xffffffffu, ps0, 2);
        ps1 += __shfl_xor_sync(0xffffffffu, ps1, 1);
        ps1 += __shfl_xor_sync(0xffffffffu, ps1, 2);
        l0 = l0 * a0 + ps0; l1 = l1 * a1 + ps1;
        m0 = mn0; m1 = mn1;
        #pragma unroll
        for (int dn = 0; dn < 8; dn++) {
            oacc[dn][0] *= a0; oacc[dn][1] *= a0;
            oacc[dn][2] *= a1; oacc[dn][3] *= a1;
        }

        #pragma unroll
        for (int kc = 0; kc < 4; kc++) {
            uint32_t af[4];
            af[0] = h2u(__floats2half2_rn(sacc[2 * kc][0],     sacc[2 * kc][1]));
            af[1] = h2u(__floats2half2_rn(sacc[2 * kc][2],     sacc[2 * kc][3]));
            af[2] = h2u(__floats2half2_rn(sacc[2 * kc + 1][0], sacc[2 * kc + 1][1]));
            af[3] = h2u(__floats2half2_rn(sacc[2 * kc + 1][2], sacc[2 * kc + 1][3]));
            uint32_t vb[8][2];
            #pragma unroll
            for (int nb = 0; nb < 4; nb++)
                ldsm4(vb[2 * nb][0], vb[2 * nb][1], vb[2 * nb + 1][0], vb[2 * nb + 1][1],
                      Vb + (uint32_t)((nb * 16 * FST + kc * 16) * 2));
            #pragma unroll
            for (int dn = 0; dn < 8; dn++)
                mma_f16(oacc[dn], af, vb[dn]);
        }

        __syncthreads();       // all warps done reading buf tt%3
        CP_WAITG(1);           // tile tt+1 resident for next iteration
    }

    // epilogue: store UNNORMALIZED partial O + (m, l) per row
    const long long r0 = rowbase + qt * 64 + warp * 16 + grp;
    float* o0 = op + (long long)half * RR * DQ + r0 * DQ;
    float* o1 = o0 + 8 * DQ;
    #pragma unroll
    for (int dn = 0; dn < 8; dn++) {
        int col = dn * 8 + 2 * tg;
        *(float2*)(o0 + col) = make_float2(oacc[dn][0], oacc[dn][1]);
        *(float2*)(o1 + col) = make_float2(oacc[dn][2], oacc[dn][3]);
    }
    if (tg == 0) {
        ml[(long long)half * RR + r0]     = make_float2(m0, l0);
        ml[(long long)half * RR + r0 + 8] = make_float2(m1, l1);
    }
}

// combine split-KV halves: warp per row, 2 cols per lane.
__global__ __launch_bounds__(256) void flash_combine_kernel(
    const float* __restrict__ op, const float2* __restrict__ ml,
    __half* __restrict__ oh)
{
    const int warp = threadIdx.x >> 5, lane = threadIdx.x & 31;
    const long long row = (long long)blockIdx.x * 8 + warp;
    float2 ml0 = ml[row], ml1 = ml[RR + row];
    float m = fmaxf(ml0.x, ml1.x);
    float a0 = __expf(ml0.x - m), a1 = __expf(ml1.x - m);
    float inv = __fdividef(1.f, ml0.y * a0 + ml1.y * a1);
    int c = lane * 2;
    float2 v0 = *(const float2*)&op[row * DQ + c];
    float2 v1 = *(const float2*)&op[(long long)RR * DQ + row * DQ + c];
    *(__half2*)&oh[row * DQ + c] = __floats2half2_rn(
        (v0.x * a0 + v1.x * a1) * inv, (v0.y * a0 + v1.y * a1) * inv);
}

// ---------------- launch ----------------------------------------------------
extern "C" void kernel_launch(void* const* d_in, const int* in_sizes, int n_in,
                              void* d_out, int out_size) {
    const float* x    = (const float*)d_in[0];
    const float* wq   = (const float*)d_in[1];
    const float* wk   = (const float*)d_in[2];
    const float* wv   = (const float*)d_in[3];
    const float* linw = (const float*)d_in[4];
    const float* linb = (const float*)d_in[5];
    const float* ln1g = (const float*)d_in[6];
    const float* ln1b = (const float*)d_in[7];
    const float* f1w  = (const float*)d_in[8];
    const float* f1b  = (const float*)d_in[9];
    const float* f2w  = (const float*)d_in[10];
    const float* f2b  = (const float*)d_in[11];
    float* out = (float*)d_out;

    void *p_h, *p_h2, *p_y1, *p_q, *p_k, *p_vt, *p_oh, *p_op, *p_ml, *p_a1;
    void *p_wsT, *p_wqkvT, *p_f1T, *p_f2T;
    cudaGetSymbolAddress(&p_h,     g_h);
    cudaGetSymbolAddress(&p_h2,    g_h2);
    cudaGetSymbolAddress(&p_y1,    g_y1);
    cudaGetSymbolAddress(&p_q,     g_q);
    cudaGetSymbolAddress(&p_k,     g_k);
    cudaGetSymbolAddress(&p_vt,    g_vt);
    cudaGetSymbolAddress(&p_oh,    g_oh);
    cudaGetSymbolAddress(&p_op,    g_op);
    cudaGetSymbolAddress(&p_ml,    g_ml);
    cudaGetSymbolAddress(&p_a1,    g_a1);
    cudaGetSymbolAddress(&p_wsT,   g_wsT);
    cudaGetSymbolAddress(&p_wqkvT, g_wqkvT);
    cudaGetSymbolAddress(&p_f1T,   g_f1T);
    cudaGetSymbolAddress(&p_f2T,   g_f2T);

    cudaFuncSetAttribute(gemm_kernel<2>,  cudaFuncAttributeMaxDynamicSharedMemorySize, GEMM_SMEM);
    cudaFuncSetAttribute(gemm_kernel<3>,  cudaFuncAttributeMaxDynamicSharedMemorySize, GEMM_SMEM);
    cudaFuncSetAttribute(qkv_gemm_kernel, cudaFuncAttributeMaxDynamicSharedMemorySize, GEMM_SMEM);
    cudaFuncSetAttribute(flash_kernel,    cudaFuncAttributeMaxDynamicSharedMemorySize, FLASH_SMEM);

    #define HP(p) ((__half*)(p))
    #define FP(p) ((float*)(p))

    wsumT_kernel<<<dim3(2, 24), dim3(32, 8)>>>(linw, HP(p_wsT));
    pack_wqkvT_kernel<<<dim3(8, 24), dim3(32, 8)>>>(wq, wk, wv, HP(p_wqkvT));
    transposeh_kernel<<<dim3(HH / 32, DD / 32), dim3(32, 8)>>>(f1w, HP(p_f1T), DD, HH);
    transposeh_kernel<<<dim3(DD / 32, HH / 32), dim3(32, 8)>>>(f2w, HP(p_f2T), HH, DD);

    // LN1: x -> h (half), warp-per-row
    ln_kernel<<<RR / 8, 256>>>(x, ln1g, ln1b, HP(p_h));

    // qkv: h @ wqkv -> q (1/8), k, v^T
    qkv_gemm_kernel<<<dim3(2, 64), 256, GEMM_SMEM>>>(HP(p_h), HP(p_wqkvT),
        HP(p_q), HP(p_k), HP(p_vt), RR, 256, DD, DD, DD);

    // flash attention, split-KV=2 -> partials, then combine -> oh (half)
    flash_kernel<<<dim3(32, 4, 2), 128, FLASH_SMEM>>>(HP(p_q), HP(p_k), HP(p_vt),
        FP(p_op), (float2*)p_ml);
    flash_combine_kernel<<<RR / 8, 256>>>(FP(p_op), (const float2*)p_ml, HP(p_oh));

    // y1 = oh @ Ws + lin_b + x  (fp32)
    gemm_kernel<2><<<dim3(6, 64), 256, GEMM_SMEM>>>(HP(p_oh), HP(p_wsT), p_y1,
        linb, x, RR, DD, DQ, DQ, DQ, DD);

    // LN2 (reuses ln1 params, matching reference): y1 -> h2 (half)
    ln_kernel<<<RR / 8, 256>>>(FP(p_y1), ln1g, ln1b, HP(p_h2));

    // a1 = gelu(h2 @ fc1 + b1)  (half)
    gemm_kernel<3><<<dim3(24, 64), 256, GEMM_SMEM>>>(HP(p_h2), HP(p_f1T), p_a1,
        f1b, nullptr, RR, HH, DD, DD, DD, HH);

    // out = a1 @ fc2 + b2 + y1  (fp32)
    gemm_kernel<2><<<dim3(6, 64), 256, GEMM_SMEM>>>(HP(p_a1), HP(p_f2T), out,
        f2b, FP(p_y1), RR, DD, HH, HH, HH, DD);
    #undef HP
    #undef FP
}